// round 1
// baseline (speedup 1.0000x reference)
#include <cuda_runtime.h>
#include <cstdint>
#include <cstddef>

// Problem constants
#define Bn 4
#define Ln 2048
#define Sn 2048
#define Dn 1024
#define Hn 16
#define En 64
#define Mrows (Bn * Ln)   // 8192 token rows

// Scratch (allocation-free: __device__ globals)
__device__ float g_q[(size_t)Bn * Hn * Ln * En];   // [B,H,L,E]
__device__ float g_k[(size_t)Bn * Hn * Sn * En];   // [B,H,S,E]
__device__ float g_v[(size_t)Bn * Hn * Sn * En];   // [B,H,S,E]
__device__ float g_ctx[(size_t)Bn * Ln * Dn];      // [B,L,D] attention output

// ---------------------------------------------------------------------------
// GEMM: C[M=8192, N=1024] = A[M,1024] @ W[1024,1024] + bias
// mode 0: write row-major C[row*N + col]
// mode 1: write split-head layout dst[((b*H + h)*L + l)*E + e]
// Tiling: BM=128, BN=64, BK=16; 256 threads; 8x4 micro-tile per thread.
// ---------------------------------------------------------------------------
__global__ __launch_bounds__(256) void gemm_bias_kernel(
    const float* __restrict__ A, const float* __restrict__ W,
    const float* __restrict__ bias, float* __restrict__ C, int mode)
{
    __shared__ float As[128][20];  // [m][k], stride 20 (16B-aligned rows, low conflict)
    __shared__ float Ws[16][68];   // [k][n], stride 68

    const int K = Dn, N = Dn;
    const int t  = threadIdx.x;
    const int tx = t & 15;
    const int ty = t >> 4;
    const int m0 = blockIdx.x * 128;
    const int n0 = blockIdx.y * 64;

    float acc[8][4];
#pragma unroll
    for (int i = 0; i < 8; i++)
#pragma unroll
        for (int j = 0; j < 4; j++) acc[i][j] = 0.f;

    for (int k0 = 0; k0 < K; k0 += 16) {
        // Load A tile 128x16 (512 float4, 2 per thread)
#pragma unroll
        for (int r = 0; r < 2; r++) {
            int idx = t + r * 256;          // 0..511
            int row = idx >> 2;             // 0..127
            int kq  = idx & 3;              // float4 slot within 16-wide k
            float4 a = *(const float4*)(A + (size_t)(m0 + row) * K + (k0 + kq * 4));
            *(float4*)&As[row][kq * 4] = a;
        }
        // Load W tile 16x64 (256 float4, 1 per thread)
        {
            int row = t >> 4;               // k within tile
            int nq  = t & 15;
            float4 w = *(const float4*)(W + (size_t)(k0 + row) * N + (n0 + nq * 4));
            *(float4*)&Ws[row][nq * 4] = w;
        }
        __syncthreads();

#pragma unroll
        for (int kk = 0; kk < 16; kk++) {
            float a[8];
#pragma unroll
            for (int i = 0; i < 8; i++) a[i] = As[ty * 8 + i][kk];
            float4 bv = *(const float4*)&Ws[kk][tx * 4];
            float bf[4] = {bv.x, bv.y, bv.z, bv.w};
#pragma unroll
            for (int i = 0; i < 8; i++)
#pragma unroll
                for (int j = 0; j < 4; j++)
                    acc[i][j] = fmaf(a[i], bf[j], acc[i][j]);
        }
        __syncthreads();
    }

    // Epilogue: + bias, write out
#pragma unroll
    for (int i = 0; i < 8; i++) {
        int row = m0 + ty * 8 + i;          // token index
#pragma unroll
        for (int j = 0; j < 4; j++) {
            int col = n0 + tx * 4 + j;      // feature index
            float v = acc[i][j] + bias[col];
            if (mode == 0) {
                C[(size_t)row * N + col] = v;
            } else {
                int b = row / Ln, l = row % Ln;
                int h = col >> 6, e = col & 63;
                C[((size_t)((b * Hn + h) * Ln) + l) * En + e] = v;
            }
        }
    }
}

// ---------------------------------------------------------------------------
// Flash attention: per block = 64 query rows of one (b,h); stream S in chunks
// of 32 with online softmax. E = 64 held fully in the block.
// q,k,v in [B,H,*,E]; ctx written in [B,L,D] row-major for the output GEMM.
// ---------------------------------------------------------------------------
__global__ __launch_bounds__(256) void attn_kernel(
    const float* __restrict__ q, const float* __restrict__ k,
    const float* __restrict__ v, float* __restrict__ ctx)
{
    __shared__ float Qs[64][68];   // [e][qrow] (transposed)
    __shared__ float Ks[64][33];   // [e][srow] (transposed)
    __shared__ float Vs[32][68];   // [srow][e]
    __shared__ float Ps[64][37];   // [qrow][srow]: scores, then probs
    __shared__ float alpha_s[64];
    __shared__ float l_s[64];

    const int t  = threadIdx.x;
    const int tx = t & 15;
    const int ty = t >> 4;
    const int q0 = blockIdx.x * 64;
    const int h  = blockIdx.y;
    const int b  = blockIdx.z;

    const float* qptr  = q + ((size_t)(b * Hn + h) * Ln + q0) * En;
    const float* kbase = k + (size_t)(b * Hn + h) * Sn * En;
    const float* vbase = v + (size_t)(b * Hn + h) * Sn * En;

    // Load Q tile 64x64 (1024 float4, 4 per thread), store transposed Qs[e][q]
#pragma unroll
    for (int r = 0; r < 4; r++) {
        int idx = t + r * 256;              // 0..1023
        int row = idx >> 4;                 // q row 0..63
        int eq  = idx & 15;
        float4 qv = *(const float4*)(qptr + (size_t)row * En + eq * 4);
        Qs[eq * 4 + 0][row] = qv.x;
        Qs[eq * 4 + 1][row] = qv.y;
        Qs[eq * 4 + 2][row] = qv.z;
        Qs[eq * 4 + 3][row] = qv.w;
    }

    float acc[4][4];
#pragma unroll
    for (int i = 0; i < 4; i++)
#pragma unroll
        for (int j = 0; j < 4; j++) acc[i][j] = 0.f;

    float m_i = -1e30f, l_i = 0.f;          // used by threads t < 64 only

    for (int s0 = 0; s0 < Sn; s0 += 32) {
        // Load K,V chunks (32x64 each; 2 float4 per thread per tensor)
#pragma unroll
        for (int r = 0; r < 2; r++) {
            int idx = t + r * 256;          // 0..511
            int row = idx >> 4;             // s row 0..31
            int eq  = idx & 15;
            float4 kv = *(const float4*)(kbase + (size_t)(s0 + row) * En + eq * 4);
            Ks[eq * 4 + 0][row] = kv.x;
            Ks[eq * 4 + 1][row] = kv.y;
            Ks[eq * 4 + 2][row] = kv.z;
            Ks[eq * 4 + 3][row] = kv.w;
            float4 vv = *(const float4*)(vbase + (size_t)(s0 + row) * En + eq * 4);
            *(float4*)&Vs[row][eq * 4] = vv;
        }
        __syncthreads();

        // Phase 1: S = scale * (Q @ K^T); micro-tile 4(q) x 2(s)
        {
            float sacc[4][2];
#pragma unroll
            for (int i = 0; i < 4; i++) { sacc[i][0] = 0.f; sacc[i][1] = 0.f; }
#pragma unroll
            for (int e = 0; e < 64; e++) {
                float a0 = Qs[e][ty * 4 + 0];
                float a1 = Qs[e][ty * 4 + 1];
                float a2 = Qs[e][ty * 4 + 2];
                float a3 = Qs[e][ty * 4 + 3];
                float b0 = Ks[e][tx * 2 + 0];
                float b1 = Ks[e][tx * 2 + 1];
                sacc[0][0] = fmaf(a0, b0, sacc[0][0]);
                sacc[0][1] = fmaf(a0, b1, sacc[0][1]);
                sacc[1][0] = fmaf(a1, b0, sacc[1][0]);
                sacc[1][1] = fmaf(a1, b1, sacc[1][1]);
                sacc[2][0] = fmaf(a2, b0, sacc[2][0]);
                sacc[2][1] = fmaf(a2, b1, sacc[2][1]);
                sacc[3][0] = fmaf(a3, b0, sacc[3][0]);
                sacc[3][1] = fmaf(a3, b1, sacc[3][1]);
            }
            const float scale = 0.125f;     // 1/sqrt(64)
#pragma unroll
            for (int i = 0; i < 4; i++) {
                Ps[ty * 4 + i][tx * 2 + 0] = sacc[i][0] * scale;
                Ps[ty * 4 + i][tx * 2 + 1] = sacc[i][1] * scale;
            }
        }
        __syncthreads();

        // Phase 2: online softmax; one thread per query row (t < 64)
        if (t < 64) {
            float m_new = m_i;
#pragma unroll
            for (int j = 0; j < 32; j++) m_new = fmaxf(m_new, Ps[t][j]);
            float alpha = __expf(m_i - m_new);
            float lsum = 0.f;
#pragma unroll
            for (int j = 0; j < 32; j++) {
                float p = __expf(Ps[t][j] - m_new);
                Ps[t][j] = p;
                lsum += p;
            }
            l_i = l_i * alpha + lsum;
            m_i = m_new;
            alpha_s[t] = alpha;
        }
        __syncthreads();

        // Phase 3: acc = acc*alpha + P @ V; micro-tile 4(q) x 4(e)
        {
            float al[4];
#pragma unroll
            for (int i = 0; i < 4; i++) al[i] = alpha_s[ty * 4 + i];
#pragma unroll
            for (int i = 0; i < 4; i++)
#pragma unroll
                for (int j = 0; j < 4; j++) acc[i][j] *= al[i];
#pragma unroll
            for (int s = 0; s < 32; s++) {
                float p0 = Ps[ty * 4 + 0][s];
                float p1 = Ps[ty * 4 + 1][s];
                float p2 = Ps[ty * 4 + 2][s];
                float p3 = Ps[ty * 4 + 3][s];
                float4 vv = *(const float4*)&Vs[s][tx * 4];
                acc[0][0] = fmaf(p0, vv.x, acc[0][0]);
                acc[0][1] = fmaf(p0, vv.y, acc[0][1]);
                acc[0][2] = fmaf(p0, vv.z, acc[0][2]);
                acc[0][3] = fmaf(p0, vv.w, acc[0][3]);
                acc[1][0] = fmaf(p1, vv.x, acc[1][0]);
                acc[1][1] = fmaf(p1, vv.y, acc[1][1]);
                acc[1][2] = fmaf(p1, vv.z, acc[1][2]);
                acc[1][3] = fmaf(p1, vv.w, acc[1][3]);
                acc[2][0] = fmaf(p2, vv.x, acc[2][0]);
                acc[2][1] = fmaf(p2, vv.y, acc[2][1]);
                acc[2][2] = fmaf(p2, vv.z, acc[2][2]);
                acc[2][3] = fmaf(p2, vv.w, acc[2][3]);
                acc[3][0] = fmaf(p3, vv.x, acc[3][0]);
                acc[3][1] = fmaf(p3, vv.y, acc[3][1]);
                acc[3][2] = fmaf(p3, vv.z, acc[3][2]);
                acc[3][3] = fmaf(p3, vv.w, acc[3][3]);
            }
        }
        __syncthreads();
    }

    if (t < 64) l_s[t] = l_i;
    __syncthreads();

    // Write ctx in [B, L, D] row-major: ctx[(b*L + q)*D + h*64 + e]
#pragma unroll
    for (int i = 0; i < 4; i++) {
        int qrow = ty * 4 + i;
        float inv = 1.f / l_s[qrow];
#pragma unroll
        for (int j = 0; j < 4; j++) {
            int e = tx * 4 + j;
            ctx[((size_t)(b * Ln + q0 + qrow)) * Dn + h * En + e] = acc[i][j] * inv;
        }
    }
}

// ---------------------------------------------------------------------------
extern "C" void kernel_launch(void* const* d_in, const int* in_sizes, int n_in,
                              void* d_out, int out_size)
{
    const float* queries = (const float*)d_in[0];
    const float* keys    = (const float*)d_in[1];
    const float* values  = (const float*)d_in[2];
    const float* Wq = (const float*)d_in[3];
    const float* bq = (const float*)d_in[4];
    const float* Wk = (const float*)d_in[5];
    const float* bk = (const float*)d_in[6];
    const float* Wv = (const float*)d_in[7];
    const float* bv = (const float*)d_in[8];
    const float* Wo = (const float*)d_in[9];
    const float* bo = (const float*)d_in[10];

    float *qbuf, *kbuf, *vbuf, *ctxbuf;
    cudaGetSymbolAddress((void**)&qbuf,   g_q);
    cudaGetSymbolAddress((void**)&kbuf,   g_k);
    cudaGetSymbolAddress((void**)&vbuf,   g_v);
    cudaGetSymbolAddress((void**)&ctxbuf, g_ctx);

    dim3 gblk(256);
    dim3 ggrid(Mrows / 128, Dn / 64);   // (64, 16)

    gemm_bias_kernel<<<ggrid, gblk>>>(queries, Wq, bq, qbuf, 1);
    gemm_bias_kernel<<<ggrid, gblk>>>(keys,    Wk, bk, kbuf, 1);
    gemm_bias_kernel<<<ggrid, gblk>>>(values,  Wv, bv, vbuf, 1);

    dim3 agrid(Ln / 64, Hn, Bn);        // (32, 16, 4)
    attn_kernel<<<agrid, 256>>>(qbuf, kbuf, vbuf, ctxbuf);

    gemm_bias_kernel<<<ggrid, gblk>>>(ctxbuf, Wo, bo, (float*)d_out, 0);
}

// round 4
// speedup vs baseline: 1.4332x; 1.4332x over previous
#include <cuda_runtime.h>
#include <cuda_bf16.h>
#include <cstdint>
#include <cstddef>

// Problem constants
#define Bn 4
#define Ln 2048
#define Sn 2048
#define Dn 1024
#define Hn 16
#define En 64
#define Mrows (Bn * Ln)   // 8192 token rows

// ---------------------------------------------------------------------------
// Scratch (allocation-free: __device__ globals)
// ---------------------------------------------------------------------------
__device__ float g_q[(size_t)Bn * Hn * Ln * En];   // [B,H,L,E]
__device__ float g_k[(size_t)Bn * Hn * Sn * En];   // [B,H,S,E]
__device__ float g_v[(size_t)Bn * Hn * Sn * En];   // [B,H,S,E]
__device__ float g_ctx[(size_t)Bn * Ln * Dn];      // [B,L,D]
__device__ __nv_bfloat16 g_ah[(size_t)Mrows * Dn]; // activation hi (bf16)
__device__ __nv_bfloat16 g_al[(size_t)Mrows * Dn]; // activation lo (bf16)
__device__ __nv_bfloat16 g_wth[4 * (size_t)Dn * Dn]; // W^T hi per matrix
__device__ __nv_bfloat16 g_wtl[4 * (size_t)Dn * Dn]; // W^T lo per matrix

// ---------------------------------------------------------------------------
// PTX helpers (sm_80-era only: cp.async + ldmatrix + mma.sync)
// ---------------------------------------------------------------------------
__device__ __forceinline__ uint32_t s2u(const void* p) {
    return (uint32_t)__cvta_generic_to_shared(p);
}
__device__ __forceinline__ void cp16(uint32_t dst, const void* src) {
    asm volatile("cp.async.cg.shared.global [%0], [%1], 16;" :: "r"(dst), "l"(src));
}
#define CP_COMMIT() asm volatile("cp.async.commit_group;" ::: "memory")
#define CP_WAIT1()  asm volatile("cp.async.wait_group 1;" ::: "memory")

#define LDSM4(r, addr) \
    asm volatile("ldmatrix.sync.aligned.m8n8.x4.shared.b16 {%0,%1,%2,%3}, [%4];" \
        : "=r"((r)[0]), "=r"((r)[1]), "=r"((r)[2]), "=r"((r)[3]) : "r"(addr))

#define MMA_BF16(d, a, b0v, b1v) \
    asm volatile("mma.sync.aligned.m16n8k16.row.col.f32.bf16.bf16.f32 " \
        "{%0,%1,%2,%3}, {%4,%5,%6,%7}, {%8,%9}, {%0,%1,%2,%3};" \
        : "+f"((d)[0]), "+f"((d)[1]), "+f"((d)[2]), "+f"((d)[3]) \
        : "r"((a)[0]), "r"((a)[1]), "r"((a)[2]), "r"((a)[3]), "r"(b0v), "r"(b1v))

// SW64 swizzle: bits[4:5] ^= bits[7:8]; conflict-free ldmatrix on 64B rows
#define SW64(o) ((o) ^ (((o) >> 3) & 0x30))

// ---------------------------------------------------------------------------
// bf16 hi/lo split of fp32 activations (elementwise, vectorized)
// ---------------------------------------------------------------------------
__global__ __launch_bounds__(256) void split_bf16_kernel(
    const float4* __restrict__ x, uint2* __restrict__ hi, uint2* __restrict__ lo, int n4)
{
    int i = blockIdx.x * 256 + threadIdx.x;
    if (i < n4) {
        float4 v = x[i];
        float vv[4] = {v.x, v.y, v.z, v.w};
        uint32_t h[4], l[4];
#pragma unroll
        for (int j = 0; j < 4; j++) {
            __nv_bfloat16 hb = __float2bfloat16_rn(vv[j]);
            float hf = __bfloat162float(hb);
            __nv_bfloat16 lb = __float2bfloat16_rn(vv[j] - hf);
            h[j] = (uint32_t)*reinterpret_cast<unsigned short*>(&hb);
            l[j] = (uint32_t)*reinterpret_cast<unsigned short*>(&lb);
        }
        hi[i] = make_uint2(h[0] | (h[1] << 16), h[2] | (h[3] << 16));
        lo[i] = make_uint2(l[0] | (l[1] << 16), l[2] | (l[3] << 16));
    }
}

// Transpose + split: W[K,N] fp32 -> Wt hi/lo bf16 [N,K]
__global__ __launch_bounds__(256) void splitT_bf16_kernel(
    const float* __restrict__ W, __nv_bfloat16* __restrict__ th,
    __nv_bfloat16* __restrict__ tl)
{
    __shared__ float ts[32][33];
    const int n0 = blockIdx.x * 32, k0 = blockIdx.y * 32;
    const int tx = threadIdx.x, ty = threadIdx.y;  // 32 x 8
#pragma unroll
    for (int r = 0; r < 4; r++) {
        int k = k0 + ty + r * 8;
        ts[ty + r * 8][tx] = W[(size_t)k * Dn + n0 + tx];
    }
    __syncthreads();
#pragma unroll
    for (int r = 0; r < 4; r++) {
        int n = n0 + ty + r * 8;
        int k = k0 + tx;
        float v = ts[tx][ty + r * 8];
        __nv_bfloat16 h = __float2bfloat16_rn(v);
        th[(size_t)n * Dn + k] = h;
        tl[(size_t)n * Dn + k] = __float2bfloat16_rn(v - __bfloat162float(h));
    }
}

// ---------------------------------------------------------------------------
// Tensor-core GEMM (3xBF16): C[M,N] = A[M,K] @ Bt[N,K]^T + bias
// BM=128, BN=128, BK=32; 256 threads = 8 warps (4m x 2n), warp tile 32x64.
// Double-buffered cp.async; SW64-swizzled smem; ldmatrix + mma.sync bf16.
// mode 0: row-major out; mode 1: split-head [B,H,L,E]
// ---------------------------------------------------------------------------
#define TILE_B   8192                 // one 128x32 bf16 tile
#define ST_BYTES (4 * TILE_B)         // Ah, Al, Bh, Bl
#define GEMM_SMEM (2 * ST_BYTES)      // 64 KB

__global__ __launch_bounds__(256) void gemm_mma_kernel(
    const __nv_bfloat16* __restrict__ Ah, const __nv_bfloat16* __restrict__ Al,
    const __nv_bfloat16* __restrict__ Bh, const __nv_bfloat16* __restrict__ Bl,
    const float* __restrict__ bias, float* __restrict__ C, int mode)
{
    extern __shared__ char smem[];
    uint32_t sb = s2u(smem);
    const int t = threadIdx.x, lane = t & 31, wid = t >> 5;
    const int wm = wid & 3, wn = wid >> 2;          // warp grid 4(m) x 2(n)
    const int m0 = blockIdx.x * 128, n0 = blockIdx.y * 128;

    // Per-thread load geometry: 512 16B-chunks per tile, 2 per thread
    int swoff[2];
    size_t goff[2];
#pragma unroll
    for (int i = 0; i < 2; i++) {
        int c = t + i * 256;            // 0..511
        int row = c >> 2;               // 0..127
        int ch  = c & 3;                // 16B chunk in 64B row
        swoff[i] = SW64(row * 64 + ch * 16);
        goff[i]  = (size_t)row * Dn + ch * 8;
    }
    const __nv_bfloat16* basep[4] = {
        Ah + (size_t)m0 * Dn, Al + (size_t)m0 * Dn,
        Bh + (size_t)n0 * Dn, Bl + (size_t)n0 * Dn };

    auto load_stage = [&](int st, int k0) {
#pragma unroll
        for (int tile = 0; tile < 4; tile++) {
            uint32_t tb = sb + st * ST_BYTES + tile * TILE_B;
            const __nv_bfloat16* gp = basep[tile] + k0;
#pragma unroll
            for (int i = 0; i < 2; i++)
                cp16(tb + swoff[i], gp + goff[i]);
        }
    };

    float acc[2][8][4];
#pragma unroll
    for (int mt = 0; mt < 2; mt++)
#pragma unroll
        for (int nt = 0; nt < 8; nt++)
#pragma unroll
            for (int j = 0; j < 4; j++) acc[mt][nt][j] = 0.f;

    load_stage(0, 0);  CP_COMMIT();
    load_stage(1, 32); CP_COMMIT();

    int cur = 0;
    for (int it = 0; it < 32; ++it) {
        CP_WAIT1();
        __syncthreads();
        uint32_t stb = sb + cur * ST_BYTES;
        uint32_t sAh = stb, sAl = stb + TILE_B;
        uint32_t sBh = stb + 2 * TILE_B, sBl = stb + 3 * TILE_B;

#pragma unroll
        for (int kk = 0; kk < 2; kk++) {
            // A fragments: rows = warp m base + (lane&15); k-half by lane&16
            int kbA = kk * 32 + ((lane & 16) ? 16 : 0);
            uint32_t ah_[2][4], al_[2][4];
#pragma unroll
            for (int mt = 0; mt < 2; mt++) {
                int r = wm * 32 + mt * 16 + (lane & 15);
                uint32_t off = SW64(r * 64 + kbA);
                LDSM4(ah_[mt], sAh + off);
                LDSM4(al_[mt], sAl + off);
            }
            // B fragments: n rows; k-half by lane&8, n-half by lane&16
            int kbB = kk * 32 + ((lane & 8) ? 16 : 0);
#pragma unroll
            for (int np = 0; np < 4; np++) {
                int nr = wn * 64 + np * 16 + (lane & 7) + ((lane & 16) ? 8 : 0);
                uint32_t off = SW64(nr * 64 + kbB);
                uint32_t bh_[4], bl_[4];
                LDSM4(bh_, sBh + off);
                LDSM4(bl_, sBl + off);
#pragma unroll
                for (int half = 0; half < 2; half++) {
                    int nt = np * 2 + half;
                    uint32_t b0h = bh_[half * 2], b1h = bh_[half * 2 + 1];
                    uint32_t b0l = bl_[half * 2], b1l = bl_[half * 2 + 1];
#pragma unroll
                    for (int mt = 0; mt < 2; mt++) {
                        MMA_BF16(acc[mt][nt], ah_[mt], b0h, b1h);  // hh
                        MMA_BF16(acc[mt][nt], ah_[mt], b0l, b1l);  // hl
                        MMA_BF16(acc[mt][nt], al_[mt], b0h, b1h);  // lh
                    }
                }
            }
        }
        __syncthreads();
        if (it + 2 < 32) load_stage(cur, (it + 2) * 32);
        CP_COMMIT();
        cur ^= 1;
    }

    // Epilogue: direct float2 stores (+bias)
#pragma unroll
    for (int mt = 0; mt < 2; mt++) {
        int grow = m0 + wm * 32 + mt * 16 + (lane >> 2);
#pragma unroll
        for (int nt = 0; nt < 8; nt++) {
            int gcol = n0 + wn * 64 + nt * 8 + (lane & 3) * 2;
            float b0 = bias[gcol], b1 = bias[gcol + 1];
            float2 v0 = make_float2(acc[mt][nt][0] + b0, acc[mt][nt][1] + b1);
            float2 v1 = make_float2(acc[mt][nt][2] + b0, acc[mt][nt][3] + b1);
            if (mode == 0) {
                *(float2*)&C[(size_t)grow * Dn + gcol] = v0;
                *(float2*)&C[(size_t)(grow + 8) * Dn + gcol] = v1;
            } else {
                int h = gcol >> 6, e = gcol & 63;
                int b_ = grow / Ln, l_ = grow % Ln;
                *(float2*)&C[((size_t)((b_ * Hn + h) * Ln) + l_) * En + e] = v0;
                int b2 = (grow + 8) / Ln, l2 = (grow + 8) % Ln;
                *(float2*)&C[((size_t)((b2 * Hn + h) * Ln) + l2) * En + e] = v1;
            }
        }
    }
}

// ---------------------------------------------------------------------------
// Flash attention (unchanged, proven fp32): 64-query tiles, online softmax.
// ---------------------------------------------------------------------------
__global__ __launch_bounds__(256) void attn_kernel(
    const float* __restrict__ q, const float* __restrict__ k,
    const float* __restrict__ v, float* __restrict__ ctx)
{
    __shared__ float Qs[64][68];
    __shared__ float Ks[64][33];
    __shared__ float Vs[32][68];
    __shared__ float Ps[64][37];
    __shared__ float alpha_s[64];
    __shared__ float l_s[64];

    const int t  = threadIdx.x;
    const int tx = t & 15;
    const int ty = t >> 4;
    const int q0 = blockIdx.x * 64;
    const int h  = blockIdx.y;
    const int b  = blockIdx.z;

    const float* qptr  = q + ((size_t)(b * Hn + h) * Ln + q0) * En;
    const float* kbase = k + (size_t)(b * Hn + h) * Sn * En;
    const float* vbase = v + (size_t)(b * Hn + h) * Sn * En;

#pragma unroll
    for (int r = 0; r < 4; r++) {
        int idx = t + r * 256;
        int row = idx >> 4;
        int eq  = idx & 15;
        float4 qv = *(const float4*)(qptr + (size_t)row * En + eq * 4);
        Qs[eq * 4 + 0][row] = qv.x;
        Qs[eq * 4 + 1][row] = qv.y;
        Qs[eq * 4 + 2][row] = qv.z;
        Qs[eq * 4 + 3][row] = qv.w;
    }

    float acc[4][4];
#pragma unroll
    for (int i = 0; i < 4; i++)
#pragma unroll
        for (int j = 0; j < 4; j++) acc[i][j] = 0.f;

    float m_i = -1e30f, l_i = 0.f;

    for (int s0 = 0; s0 < Sn; s0 += 32) {
#pragma unroll
        for (int r = 0; r < 2; r++) {
            int idx = t + r * 256;
            int row = idx >> 4;
            int eq  = idx & 15;
            float4 kv = *(const float4*)(kbase + (size_t)(s0 + row) * En + eq * 4);
            Ks[eq * 4 + 0][row] = kv.x;
            Ks[eq * 4 + 1][row] = kv.y;
            Ks[eq * 4 + 2][row] = kv.z;
            Ks[eq * 4 + 3][row] = kv.w;
            float4 vv = *(const float4*)(vbase + (size_t)(s0 + row) * En + eq * 4);
            *(float4*)&Vs[row][eq * 4] = vv;
        }
        __syncthreads();

        {
            float sacc[4][2];
#pragma unroll
            for (int i = 0; i < 4; i++) { sacc[i][0] = 0.f; sacc[i][1] = 0.f; }
#pragma unroll
            for (int e = 0; e < 64; e++) {
                float a0 = Qs[e][ty * 4 + 0];
                float a1 = Qs[e][ty * 4 + 1];
                float a2 = Qs[e][ty * 4 + 2];
                float a3 = Qs[e][ty * 4 + 3];
                float b0 = Ks[e][tx * 2 + 0];
                float b1 = Ks[e][tx * 2 + 1];
                sacc[0][0] = fmaf(a0, b0, sacc[0][0]);
                sacc[0][1] = fmaf(a0, b1, sacc[0][1]);
                sacc[1][0] = fmaf(a1, b0, sacc[1][0]);
                sacc[1][1] = fmaf(a1, b1, sacc[1][1]);
                sacc[2][0] = fmaf(a2, b0, sacc[2][0]);
                sacc[2][1] = fmaf(a2, b1, sacc[2][1]);
                sacc[3][0] = fmaf(a3, b0, sacc[3][0]);
                sacc[3][1] = fmaf(a3, b1, sacc[3][1]);
            }
            const float scale = 0.125f;
#pragma unroll
            for (int i = 0; i < 4; i++) {
                Ps[ty * 4 + i][tx * 2 + 0] = sacc[i][0] * scale;
                Ps[ty * 4 + i][tx * 2 + 1] = sacc[i][1] * scale;
            }
        }
        __syncthreads();

        if (t < 64) {
            float m_new = m_i;
#pragma unroll
            for (int j = 0; j < 32; j++) m_new = fmaxf(m_new, Ps[t][j]);
            float alpha = __expf(m_i - m_new);
            float lsum = 0.f;
#pragma unroll
            for (int j = 0; j < 32; j++) {
                float p = __expf(Ps[t][j] - m_new);
                Ps[t][j] = p;
                lsum += p;
            }
            l_i = l_i * alpha + lsum;
            m_i = m_new;
            alpha_s[t] = alpha;
        }
        __syncthreads();

        {
            float al[4];
#pragma unroll
            for (int i = 0; i < 4; i++) al[i] = alpha_s[ty * 4 + i];
#pragma unroll
            for (int i = 0; i < 4; i++)
#pragma unroll
                for (int j = 0; j < 4; j++) acc[i][j] *= al[i];
#pragma unroll
            for (int s = 0; s < 32; s++) {
                float p0 = Ps[ty * 4 + 0][s];
                float p1 = Ps[ty * 4 + 1][s];
                float p2 = Ps[ty * 4 + 2][s];
                float p3 = Ps[ty * 4 + 3][s];
                float4 vv = *(const float4*)&Vs[s][tx * 4];
                acc[0][0] = fmaf(p0, vv.x, acc[0][0]);
                acc[0][1] = fmaf(p0, vv.y, acc[0][1]);
                acc[0][2] = fmaf(p0, vv.z, acc[0][2]);
                acc[0][3] = fmaf(p0, vv.w, acc[0][3]);
                acc[1][0] = fmaf(p1, vv.x, acc[1][0]);
                acc[1][1] = fmaf(p1, vv.y, acc[1][1]);
                acc[1][2] = fmaf(p1, vv.z, acc[1][2]);
                acc[1][3] = fmaf(p1, vv.w, acc[1][3]);
                acc[2][0] = fmaf(p2, vv.x, acc[2][0]);
                acc[2][1] = fmaf(p2, vv.y, acc[2][1]);
                acc[2][2] = fmaf(p2, vv.z, acc[2][2]);
                acc[2][3] = fmaf(p2, vv.w, acc[2][3]);
                acc[3][0] = fmaf(p3, vv.x, acc[3][0]);
                acc[3][1] = fmaf(p3, vv.y, acc[3][1]);
                acc[3][2] = fmaf(p3, vv.z, acc[3][2]);
                acc[3][3] = fmaf(p3, vv.w, acc[3][3]);
            }
        }
        __syncthreads();
    }

    if (t < 64) l_s[t] = l_i;
    __syncthreads();

#pragma unroll
    for (int i = 0; i < 4; i++) {
        int qrow = ty * 4 + i;
        float inv = 1.f / l_s[qrow];
#pragma unroll
        for (int j = 0; j < 4; j++) {
            int e = tx * 4 + j;
            ctx[((size_t)(b * Ln + q0 + qrow)) * Dn + h * En + e] = acc[i][j] * inv;
        }
    }
}

// ---------------------------------------------------------------------------
extern "C" void kernel_launch(void* const* d_in, const int* in_sizes, int n_in,
                              void* d_out, int out_size)
{
    const float* queries = (const float*)d_in[0];
    const float* keys    = (const float*)d_in[1];
    const float* values  = (const float*)d_in[2];
    const float* Wq = (const float*)d_in[3];
    const float* bq = (const float*)d_in[4];
    const float* Wk = (const float*)d_in[5];
    const float* bk = (const float*)d_in[6];
    const float* Wv = (const float*)d_in[7];
    const float* bv = (const float*)d_in[8];
    const float* Wo = (const float*)d_in[9];
    const float* bo = (const float*)d_in[10];

    float *qbuf, *kbuf, *vbuf, *ctxbuf;
    __nv_bfloat16 *ah, *al, *wth, *wtl;
    cudaGetSymbolAddress((void**)&qbuf,   g_q);
    cudaGetSymbolAddress((void**)&kbuf,   g_k);
    cudaGetSymbolAddress((void**)&vbuf,   g_v);
    cudaGetSymbolAddress((void**)&ctxbuf, g_ctx);
    cudaGetSymbolAddress((void**)&ah,     g_ah);
    cudaGetSymbolAddress((void**)&al,     g_al);
    cudaGetSymbolAddress((void**)&wth,    g_wth);
    cudaGetSymbolAddress((void**)&wtl,    g_wtl);

    cudaFuncSetAttribute(gemm_mma_kernel,
                         cudaFuncAttributeMaxDynamicSharedMemorySize, GEMM_SMEM);

    const size_t WSZ = (size_t)Dn * Dn;
    dim3 tgrid(32, 32), tblk(32, 8);
    splitT_bf16_kernel<<<tgrid, tblk>>>(Wq, wth + 0 * WSZ, wtl + 0 * WSZ);
    splitT_bf16_kernel<<<tgrid, tblk>>>(Wk, wth + 1 * WSZ, wtl + 1 * WSZ);
    splitT_bf16_kernel<<<tgrid, tblk>>>(Wv, wth + 2 * WSZ, wtl + 2 * WSZ);
    splitT_bf16_kernel<<<tgrid, tblk>>>(Wo, wth + 3 * WSZ, wtl + 3 * WSZ);

    const int n4 = Mrows * Dn / 4;
    dim3 ggrid(Mrows / 128, Dn / 128);   // (64, 8)

    // Q projection
    split_bf16_kernel<<<n4 / 256, 256>>>((const float4*)queries, (uint2*)ah, (uint2*)al, n4);
    gemm_mma_kernel<<<ggrid, 256, GEMM_SMEM>>>(ah, al, wth + 0 * WSZ, wtl + 0 * WSZ, bq, qbuf, 1);
    // K projection
    split_bf16_kernel<<<n4 / 256, 256>>>((const float4*)keys, (uint2*)ah, (uint2*)al, n4);
    gemm_mma_kernel<<<ggrid, 256, GEMM_SMEM>>>(ah, al, wth + 1 * WSZ, wtl + 1 * WSZ, bk, kbuf, 1);
    // V projection
    split_bf16_kernel<<<n4 / 256, 256>>>((const float4*)values, (uint2*)ah, (uint2*)al, n4);
    gemm_mma_kernel<<<ggrid, 256, GEMM_SMEM>>>(ah, al, wth + 2 * WSZ, wtl + 2 * WSZ, bv, vbuf, 1);

    // Attention
    dim3 agrid(Ln / 64, Hn, Bn);
    attn_kernel<<<agrid, 256>>>(qbuf, kbuf, vbuf, ctxbuf);

    // Output projection
    split_bf16_kernel<<<n4 / 256, 256>>>((const float4*)ctxbuf, (uint2*)ah, (uint2*)al, n4);
    gemm_mma_kernel<<<ggrid, 256, GEMM_SMEM>>>(ah, al, wth + 3 * WSZ, wtl + 3 * WSZ, bo, (float*)d_out, 0);
}

// round 6
// speedup vs baseline: 3.2277x; 2.2520x over previous
#include <cuda_runtime.h>
#include <cuda_bf16.h>
#include <cstdint>
#include <cstddef>

// Problem constants
#define Bn 4
#define Ln 2048
#define Sn 2048
#define Dn 1024
#define Hn 16
#define En 64
#define Mrows (Bn * Ln)   // 8192 token rows

// ---------------------------------------------------------------------------
// Scratch (allocation-free: __device__ globals)
// ---------------------------------------------------------------------------
__device__ float g_ctx[(size_t)Bn * Ln * Dn];        // [B,L,D]
__device__ __nv_bfloat16 g_ah[(size_t)Mrows * Dn];   // activation hi (bf16)
__device__ __nv_bfloat16 g_al[(size_t)Mrows * Dn];   // activation lo (bf16)
__device__ __nv_bfloat16 g_wth[4 * (size_t)Dn * Dn]; // W^T hi per matrix
__device__ __nv_bfloat16 g_wtl[4 * (size_t)Dn * Dn]; // W^T lo per matrix
// Q/K/V in split-head [B,H,*,E], bf16 hi/lo
__device__ __nv_bfloat16 g_qh[(size_t)Bn * Hn * Ln * En];
__device__ __nv_bfloat16 g_ql[(size_t)Bn * Hn * Ln * En];
__device__ __nv_bfloat16 g_kh[(size_t)Bn * Hn * Sn * En];
__device__ __nv_bfloat16 g_kl[(size_t)Bn * Hn * Sn * En];
__device__ __nv_bfloat16 g_vh[(size_t)Bn * Hn * Sn * En];
__device__ __nv_bfloat16 g_vl[(size_t)Bn * Hn * Sn * En];

// ---------------------------------------------------------------------------
// PTX helpers (sm_80-era only: cp.async + ldmatrix + mma.sync)
// ---------------------------------------------------------------------------
__device__ __forceinline__ uint32_t s2u(const void* p) {
    return (uint32_t)__cvta_generic_to_shared(p);
}
__device__ __forceinline__ void cp16(uint32_t dst, const void* src) {
    asm volatile("cp.async.cg.shared.global [%0], [%1], 16;" :: "r"(dst), "l"(src));
}
#define CP_COMMIT() asm volatile("cp.async.commit_group;" ::: "memory")
#define CP_WAIT1()  asm volatile("cp.async.wait_group 1;" ::: "memory")

#define LDSM4(r, addr) \
    asm volatile("ldmatrix.sync.aligned.m8n8.x4.shared.b16 {%0,%1,%2,%3}, [%4];" \
        : "=r"((r)[0]), "=r"((r)[1]), "=r"((r)[2]), "=r"((r)[3]) : "r"(addr))

#define LDSM4T(r, addr) \
    asm volatile("ldmatrix.sync.aligned.m8n8.x4.trans.shared.b16 {%0,%1,%2,%3}, [%4];" \
        : "=r"((r)[0]), "=r"((r)[1]), "=r"((r)[2]), "=r"((r)[3]) : "r"(addr))

#define MMA_BF16(d, a, b0v, b1v) \
    asm volatile("mma.sync.aligned.m16n8k16.row.col.f32.bf16.bf16.f32 " \
        "{%0,%1,%2,%3}, {%4,%5,%6,%7}, {%8,%9}, {%0,%1,%2,%3};" \
        : "+f"((d)[0]), "+f"((d)[1]), "+f"((d)[2]), "+f"((d)[3]) \
        : "r"((a)[0]), "r"((a)[1]), "r"((a)[2]), "r"((a)[3]), "r"(b0v), "r"(b1v))

// Swizzles: SW64 for 64B rows (gemm), SW128 for 128B rows (attention)
#define SW64(o)  ((o) ^ (((o) >> 3) & 0x30))
#define SW128(o) ((o) ^ (((o) >> 3) & 0x70))

__device__ __forceinline__ float ex2f(float x) {
    float y;
    asm("ex2.approx.ftz.f32 %0, %1;" : "=f"(y) : "f"(x));
    return y;
}
// Pack (even,odd) fp32 pair -> bf16x2 hi + bf16x2 residual-lo
__device__ __forceinline__ void pack_hilo(float e, float o, uint32_t& ph, uint32_t& pl) {
    asm("cvt.rn.bf16x2.f32 %0, %1, %2;" : "=r"(ph) : "f"(o), "f"(e));
    float fe = __uint_as_float(ph << 16);
    float fo = __uint_as_float(ph & 0xFFFF0000u);
    float re = e - fe, ro = o - fo;
    asm("cvt.rn.bf16x2.f32 %0, %1, %2;" : "=r"(pl) : "f"(ro), "f"(re));
}

// ---------------------------------------------------------------------------
// bf16 hi/lo split of fp32 activations
// ---------------------------------------------------------------------------
__global__ __launch_bounds__(256) void split_bf16_kernel(
    const float4* __restrict__ x, uint2* __restrict__ hi, uint2* __restrict__ lo, int n4)
{
    int i = blockIdx.x * 256 + threadIdx.x;
    if (i < n4) {
        float4 v = x[i];
        uint32_t p0h, p0l, p1h, p1l;
        pack_hilo(v.x, v.y, p0h, p0l);
        pack_hilo(v.z, v.w, p1h, p1l);
        hi[i] = make_uint2(p0h, p1h);
        lo[i] = make_uint2(p0l, p1l);
    }
}

// Transpose + split: W[K,N] fp32 -> Wt hi/lo bf16 [N,K]
__global__ __launch_bounds__(256) void splitT_bf16_kernel(
    const float* __restrict__ W, __nv_bfloat16* __restrict__ th,
    __nv_bfloat16* __restrict__ tl)
{
    __shared__ float ts[32][33];
    const int n0 = blockIdx.x * 32, k0 = blockIdx.y * 32;
    const int tx = threadIdx.x, ty = threadIdx.y;  // 32 x 8
#pragma unroll
    for (int r = 0; r < 4; r++) {
        int k = k0 + ty + r * 8;
        ts[ty + r * 8][tx] = W[(size_t)k * Dn + n0 + tx];
    }
    __syncthreads();
#pragma unroll
    for (int r = 0; r < 4; r++) {
        int n = n0 + ty + r * 8;
        int k = k0 + tx;
        float v = ts[tx][ty + r * 8];
        __nv_bfloat16 h = __float2bfloat16_rn(v);
        th[(size_t)n * Dn + k] = h;
        tl[(size_t)n * Dn + k] = __float2bfloat16_rn(v - __bfloat162float(h));
    }
}

// ---------------------------------------------------------------------------
// Tensor-core GEMM (3xBF16): mode 0: fp32 row-major; mode 2: bf16 hi/lo
// split-head [B,H,L,E]. BM=BN=128, BK=32, 8 warps.
// ---------------------------------------------------------------------------
#define TILE_B   8192
#define ST_BYTES (4 * TILE_B)
#define GEMM_SMEM (2 * ST_BYTES)

__global__ __launch_bounds__(256) void gemm_mma_kernel(
    const __nv_bfloat16* __restrict__ Ah, const __nv_bfloat16* __restrict__ Al,
    const __nv_bfloat16* __restrict__ Bh, const __nv_bfloat16* __restrict__ Bl,
    const float* __restrict__ bias, float* __restrict__ C,
    __nv_bfloat16* __restrict__ Ch, __nv_bfloat16* __restrict__ Cl, int mode)
{
    extern __shared__ char smem[];
    uint32_t sb = s2u(smem);
    const int t = threadIdx.x, lane = t & 31, wid = t >> 5;
    const int wm = wid & 3, wn = wid >> 2;
    const int m0 = blockIdx.x * 128, n0 = blockIdx.y * 128;

    int swoff[2];
    size_t goff[2];
#pragma unroll
    for (int i = 0; i < 2; i++) {
        int c = t + i * 256;
        int row = c >> 2;
        int ch  = c & 3;
        swoff[i] = SW64(row * 64 + ch * 16);
        goff[i]  = (size_t)row * Dn + ch * 8;
    }
    const __nv_bfloat16* basep[4] = {
        Ah + (size_t)m0 * Dn, Al + (size_t)m0 * Dn,
        Bh + (size_t)n0 * Dn, Bl + (size_t)n0 * Dn };

    auto load_stage = [&](int st, int k0) {
#pragma unroll
        for (int tile = 0; tile < 4; tile++) {
            uint32_t tb = sb + st * ST_BYTES + tile * TILE_B;
            const __nv_bfloat16* gp = basep[tile] + k0;
#pragma unroll
            for (int i = 0; i < 2; i++)
                cp16(tb + swoff[i], gp + goff[i]);
        }
    };

    float acc[2][8][4];
#pragma unroll
    for (int mt = 0; mt < 2; mt++)
#pragma unroll
        for (int nt = 0; nt < 8; nt++)
#pragma unroll
            for (int j = 0; j < 4; j++) acc[mt][nt][j] = 0.f;

    load_stage(0, 0);  CP_COMMIT();
    load_stage(1, 32); CP_COMMIT();

    int cur = 0;
    for (int it = 0; it < 32; ++it) {
        CP_WAIT1();
        __syncthreads();
        uint32_t stb = sb + cur * ST_BYTES;
        uint32_t sAh = stb, sAl = stb + TILE_B;
        uint32_t sBh = stb + 2 * TILE_B, sBl = stb + 3 * TILE_B;

#pragma unroll
        for (int kk = 0; kk < 2; kk++) {
            int kbA = kk * 32 + ((lane & 16) ? 16 : 0);
            uint32_t ah_[2][4], al_[2][4];
#pragma unroll
            for (int mt = 0; mt < 2; mt++) {
                int r = wm * 32 + mt * 16 + (lane & 15);
                uint32_t off = SW64(r * 64 + kbA);
                LDSM4(ah_[mt], sAh + off);
                LDSM4(al_[mt], sAl + off);
            }
            int kbB = kk * 32 + ((lane & 8) ? 16 : 0);
#pragma unroll
            for (int np = 0; np < 4; np++) {
                int nr = wn * 64 + np * 16 + (lane & 7) + ((lane & 16) ? 8 : 0);
                uint32_t off = SW64(nr * 64 + kbB);
                uint32_t bh_[4], bl_[4];
                LDSM4(bh_, sBh + off);
                LDSM4(bl_, sBl + off);
#pragma unroll
                for (int half = 0; half < 2; half++) {
                    int nt = np * 2 + half;
                    uint32_t b0h = bh_[half * 2], b1h = bh_[half * 2 + 1];
                    uint32_t b0l = bl_[half * 2], b1l = bl_[half * 2 + 1];
#pragma unroll
                    for (int mt = 0; mt < 2; mt++) {
                        MMA_BF16(acc[mt][nt], ah_[mt], b0h, b1h);  // hh
                        MMA_BF16(acc[mt][nt], ah_[mt], b0l, b1l);  // hl
                        MMA_BF16(acc[mt][nt], al_[mt], b0h, b1h);  // lh
                    }
                }
            }
        }
        __syncthreads();
        if (it + 2 < 32) load_stage(cur, (it + 2) * 32);
        CP_COMMIT();
        cur ^= 1;
    }

#pragma unroll
    for (int mt = 0; mt < 2; mt++) {
        int grow = m0 + wm * 32 + mt * 16 + (lane >> 2);
#pragma unroll
        for (int nt = 0; nt < 8; nt++) {
            int gcol = n0 + wn * 64 + nt * 8 + (lane & 3) * 2;
            float b0 = bias[gcol], b1 = bias[gcol + 1];
            float v00 = acc[mt][nt][0] + b0, v01 = acc[mt][nt][1] + b1;
            float v10 = acc[mt][nt][2] + b0, v11 = acc[mt][nt][3] + b1;
            if (mode == 0) {
                *(float2*)&C[(size_t)grow * Dn + gcol] = make_float2(v00, v01);
                *(float2*)&C[(size_t)(grow + 8) * Dn + gcol] = make_float2(v10, v11);
            } else {
                int hh = gcol >> 6, e = gcol & 63;
                int b_ = grow / Ln, l_ = grow % Ln;
                size_t i0 = ((size_t)((b_ * Hn + hh) * Ln) + l_) * En + e;
                int b2 = (grow + 8) / Ln, l2 = (grow + 8) % Ln;
                size_t i1 = ((size_t)((b2 * Hn + hh) * Ln) + l2) * En + e;
                uint32_t ph, pl;
                pack_hilo(v00, v01, ph, pl);
                *(uint32_t*)&Ch[i0] = ph;
                *(uint32_t*)&Cl[i0] = pl;
                pack_hilo(v10, v11, ph, pl);
                *(uint32_t*)&Ch[i1] = ph;
                *(uint32_t*)&Cl[i1] = pl;
            }
        }
    }
}

// ---------------------------------------------------------------------------
// Flash attention, tensor-core (3xBF16 both matmuls).
// Block: 8 warps x 16 q-rows = 128 rows of one (b,h). S streamed in 64-chunks.
// smem: Q hi/lo 32KB + 2 stages x (K hi/lo + V hi/lo = 32KB) = 96KB dynamic.
// ---------------------------------------------------------------------------
#define AT_QH 0
#define AT_QL 16384
#define AT_ST 32768          // stage base
#define AT_STSZ 32768        // per stage: KH 0, KL 8192, VH 16384, VL 24576
#define ATTN_SMEM (AT_ST + 2 * AT_STSZ)   // 98304

__global__ __launch_bounds__(256) void attn_mma_kernel(
    const __nv_bfloat16* __restrict__ qh, const __nv_bfloat16* __restrict__ ql,
    const __nv_bfloat16* __restrict__ kh, const __nv_bfloat16* __restrict__ kl,
    const __nv_bfloat16* __restrict__ vh, const __nv_bfloat16* __restrict__ vl,
    float* __restrict__ ctx)
{
    extern __shared__ char smem[];
    uint32_t sb = s2u(smem);
    const int t = threadIdx.x, lane = t & 31, wid = t >> 5;
    const int q0 = blockIdx.x * 128, h = blockIdx.y, b = blockIdx.z;
    const size_t bh = (size_t)(b * Hn + h);

    const __nv_bfloat16* qhp = qh + (bh * Ln + q0) * En;
    const __nv_bfloat16* qlp = ql + (bh * Ln + q0) * En;
    const __nv_bfloat16* khp = kh + bh * Sn * En;
    const __nv_bfloat16* klp = kl + bh * Sn * En;
    const __nv_bfloat16* vhp = vh + bh * Sn * En;
    const __nv_bfloat16* vlp = vl + bh * Sn * En;

    // Load Q hi/lo (128 x 64 bf16 each = 16KB each)
#pragma unroll
    for (int i = 0; i < 4; i++) {
        int c = t + i * 256;          // 0..1023
        int row = c >> 3, ch = c & 7;
        uint32_t off = SW128(row * 128 + ch * 16);
        size_t g = (size_t)row * En + ch * 8;
        cp16(sb + AT_QH + off, qhp + g);
        cp16(sb + AT_QL + off, qlp + g);
    }
    CP_COMMIT();

    auto load_kv = [&](int st, int s0) {
        uint32_t stb = sb + AT_ST + st * AT_STSZ;
#pragma unroll
        for (int i = 0; i < 2; i++) {
            int c = t + i * 256;      // 0..511
            int row = c >> 3, ch = c & 7;
            uint32_t off = SW128(row * 128 + ch * 16);
            size_t g = (size_t)(s0 + row) * En + ch * 8;
            cp16(stb + 0     + off, khp + g);
            cp16(stb + 8192  + off, klp + g);
            cp16(stb + 16384 + off, vhp + g);
            cp16(stb + 24576 + off, vlp + g);
        }
    };
    load_kv(0, 0);  CP_COMMIT();
    load_kv(1, 64); CP_COMMIT();

    CP_WAIT1();
    __syncthreads();

    // Q A-fragments (register-resident for whole kernel)
    uint32_t qa_h[4][4], qa_l[4][4];
    {
        int r = wid * 16 + (lane & 15);
#pragma unroll
        for (int kk = 0; kk < 4; kk++) {
            int kb = kk * 32 + ((lane & 16) ? 16 : 0);
            uint32_t off = SW128(r * 128 + kb);
            LDSM4(qa_h[kk], sb + AT_QH + off);
            LDSM4(qa_l[kk], sb + AT_QL + off);
        }
    }

    float acc[8][4];
#pragma unroll
    for (int e = 0; e < 8; e++)
#pragma unroll
        for (int j = 0; j < 4; j++) acc[e][j] = 0.f;
    float m0r = -1e30f, m1r = -1e30f, l0 = 0.f, l1 = 0.f;
    const float SC = 0.125f * 1.4426950408889634f;   // scale * log2(e)

    int cur = 0;
    for (int it = 0; it < 32; ++it) {
        CP_WAIT1();
        __syncthreads();
        uint32_t stb = sb + AT_ST + cur * AT_STSZ;

        // ---- QK^T: scores m16 x n64 (8 n-tiles), 3-pass bf16 ----
        float s_[8][4];
#pragma unroll
        for (int nt = 0; nt < 8; nt++)
#pragma unroll
            for (int j = 0; j < 4; j++) s_[nt][j] = 0.f;

#pragma unroll
        for (int kk = 0; kk < 4; kk++) {
            int kb = kk * 32 + ((lane & 8) ? 16 : 0);
#pragma unroll
            for (int np = 0; np < 4; np++) {
                int nr = np * 16 + (lane & 7) + ((lane & 16) ? 8 : 0);
                uint32_t off = SW128(nr * 128 + kb);
                uint32_t bh_[4], bl_[4];
                LDSM4(bh_, stb + 0 + off);
                LDSM4(bl_, stb + 8192 + off);
#pragma unroll
                for (int hf = 0; hf < 2; hf++) {
                    int nt = np * 2 + hf;
                    uint32_t b0h = bh_[hf * 2], b1h = bh_[hf * 2 + 1];
                    uint32_t b0l = bl_[hf * 2], b1l = bl_[hf * 2 + 1];
                    MMA_BF16(s_[nt], qa_h[kk], b0h, b1h);
                    MMA_BF16(s_[nt], qa_h[kk], b0l, b1l);
                    MMA_BF16(s_[nt], qa_l[kk], b0h, b1h);
                }
            }
        }

        // ---- online softmax (rows r=lane>>2 and r+8) ----
        float mx0 = m0r, mx1 = m1r;
#pragma unroll
        for (int nt = 0; nt < 8; nt++) {
            mx0 = fmaxf(mx0, fmaxf(s_[nt][0], s_[nt][1]));
            mx1 = fmaxf(mx1, fmaxf(s_[nt][2], s_[nt][3]));
        }
        mx0 = fmaxf(mx0, __shfl_xor_sync(0xFFFFFFFFu, mx0, 1));
        mx0 = fmaxf(mx0, __shfl_xor_sync(0xFFFFFFFFu, mx0, 2));
        mx1 = fmaxf(mx1, __shfl_xor_sync(0xFFFFFFFFu, mx1, 1));
        mx1 = fmaxf(mx1, __shfl_xor_sync(0xFFFFFFFFu, mx1, 2));
        float a0 = ex2f(SC * (m0r - mx0));
        float a1 = ex2f(SC * (m1r - mx1));
        m0r = mx0; m1r = mx1;
        float cm0 = SC * mx0, cm1 = SC * mx1;
        l0 *= a0; l1 *= a1;
#pragma unroll
        for (int e = 0; e < 8; e++) {
            acc[e][0] *= a0; acc[e][1] *= a0;
            acc[e][2] *= a1; acc[e][3] *= a1;
        }
        float ps0 = 0.f, ps1 = 0.f;
#pragma unroll
        for (int nt = 0; nt < 8; nt++) {
            s_[nt][0] = ex2f(fmaf(s_[nt][0], SC, -cm0));
            s_[nt][1] = ex2f(fmaf(s_[nt][1], SC, -cm0));
            s_[nt][2] = ex2f(fmaf(s_[nt][2], SC, -cm1));
            s_[nt][3] = ex2f(fmaf(s_[nt][3], SC, -cm1));
            ps0 += s_[nt][0] + s_[nt][1];
            ps1 += s_[nt][2] + s_[nt][3];
        }
        l0 += ps0; l1 += ps1;

        // ---- P @ V: 3-pass bf16; P frags from registers, V via ldmatrix.trans ----
#pragma unroll
        for (int j = 0; j < 4; j++) {       // k16 steps over s-chunk
            uint32_t pa_h[4], pa_l[4];
            pack_hilo(s_[2*j][0],   s_[2*j][1],   pa_h[0], pa_l[0]);
            pack_hilo(s_[2*j][2],   s_[2*j][3],   pa_h[1], pa_l[1]);
            pack_hilo(s_[2*j+1][0], s_[2*j+1][1], pa_h[2], pa_l[2]);
            pack_hilo(s_[2*j+1][2], s_[2*j+1][3], pa_h[3], pa_l[3]);
#pragma unroll
            for (int ne = 0; ne < 4; ne++) { // e 16-col groups
                int srow = j * 16 + (lane & 7) + ((lane & 8) ? 8 : 0);
                int ecol = ne * 16 + ((lane & 16) ? 8 : 0);
                uint32_t off = SW128(srow * 128 + ecol * 2);
                uint32_t v_h[4], v_l[4];
                LDSM4T(v_h, stb + 16384 + off);
                LDSM4T(v_l, stb + 24576 + off);
#pragma unroll
                for (int hf = 0; hf < 2; hf++) {
                    int et = ne * 2 + hf;
                    uint32_t b0h = v_h[hf * 2], b1h = v_h[hf * 2 + 1];
                    uint32_t b0l = v_l[hf * 2], b1l = v_l[hf * 2 + 1];
                    MMA_BF16(acc[et], pa_h, b0h, b1h);
                    MMA_BF16(acc[et], pa_h, b0l, b1l);
                    MMA_BF16(acc[et], pa_l, b0h, b1h);
                }
            }
        }

        __syncthreads();
        if (it + 2 < 32) load_kv(cur, (it + 2) * 64);
        CP_COMMIT();
        cur ^= 1;
    }

    // Final: reduce l across quad, normalize, write ctx [B,L,D]
    l0 += __shfl_xor_sync(0xFFFFFFFFu, l0, 1);
    l0 += __shfl_xor_sync(0xFFFFFFFFu, l0, 2);
    l1 += __shfl_xor_sync(0xFFFFFFFFu, l1, 1);
    l1 += __shfl_xor_sync(0xFFFFFFFFu, l1, 2);
    float inv0 = 1.f / l0, inv1 = 1.f / l1;

    int gr0 = q0 + wid * 16 + (lane >> 2);
    float* cp0 = ctx + ((size_t)(b * Ln + gr0)) * Dn + h * En;
    float* cp1 = cp0 + (size_t)8 * Dn;
#pragma unroll
    for (int et = 0; et < 8; et++) {
        int e = et * 8 + (lane & 3) * 2;
        *(float2*)(cp0 + e) = make_float2(acc[et][0] * inv0, acc[et][1] * inv0);
        *(float2*)(cp1 + e) = make_float2(acc[et][2] * inv1, acc[et][3] * inv1);
    }
}

// ---------------------------------------------------------------------------
extern "C" void kernel_launch(void* const* d_in, const int* in_sizes, int n_in,
                              void* d_out, int out_size)
{
    const float* queries = (const float*)d_in[0];
    const float* keys    = (const float*)d_in[1];
    const float* values  = (const float*)d_in[2];
    const float* Wq = (const float*)d_in[3];
    const float* bq = (const float*)d_in[4];
    const float* Wk = (const float*)d_in[5];
    const float* bk = (const float*)d_in[6];
    const float* Wv = (const float*)d_in[7];
    const float* bv = (const float*)d_in[8];
    const float* Wo = (const float*)d_in[9];
    const float* bo = (const float*)d_in[10];

    float *ctxbuf;
    __nv_bfloat16 *ah, *al, *wth, *wtl, *qh_, *ql_, *kh_, *kl_, *vh_, *vl_;
    cudaGetSymbolAddress((void**)&ctxbuf, g_ctx);
    cudaGetSymbolAddress((void**)&ah,  g_ah);
    cudaGetSymbolAddress((void**)&al,  g_al);
    cudaGetSymbolAddress((void**)&wth, g_wth);
    cudaGetSymbolAddress((void**)&wtl, g_wtl);
    cudaGetSymbolAddress((void**)&qh_, g_qh);
    cudaGetSymbolAddress((void**)&ql_, g_ql);
    cudaGetSymbolAddress((void**)&kh_, g_kh);
    cudaGetSymbolAddress((void**)&kl_, g_kl);
    cudaGetSymbolAddress((void**)&vh_, g_vh);
    cudaGetSymbolAddress((void**)&vl_, g_vl);

    cudaFuncSetAttribute(gemm_mma_kernel,
                         cudaFuncAttributeMaxDynamicSharedMemorySize, GEMM_SMEM);
    cudaFuncSetAttribute(attn_mma_kernel,
                         cudaFuncAttributeMaxDynamicSharedMemorySize, ATTN_SMEM);

    const size_t WSZ = (size_t)Dn * Dn;
    dim3 tgrid(32, 32), tblk(32, 8);
    splitT_bf16_kernel<<<tgrid, tblk>>>(Wq, wth + 0 * WSZ, wtl + 0 * WSZ);
    splitT_bf16_kernel<<<tgrid, tblk>>>(Wk, wth + 1 * WSZ, wtl + 1 * WSZ);
    splitT_bf16_kernel<<<tgrid, tblk>>>(Wv, wth + 2 * WSZ, wtl + 2 * WSZ);
    splitT_bf16_kernel<<<tgrid, tblk>>>(Wo, wth + 3 * WSZ, wtl + 3 * WSZ);

    const int n4 = Mrows * Dn / 4;
    dim3 ggrid(Mrows / 128, Dn / 128);   // (64, 8)

    // Q/K/V projections -> bf16 hi/lo split-head (mode 2)
    split_bf16_kernel<<<n4 / 256, 256>>>((const float4*)queries, (uint2*)ah, (uint2*)al, n4);
    gemm_mma_kernel<<<ggrid, 256, GEMM_SMEM>>>(ah, al, wth + 0 * WSZ, wtl + 0 * WSZ, bq,
                                               nullptr, qh_, ql_, 2);
    split_bf16_kernel<<<n4 / 256, 256>>>((const float4*)keys, (uint2*)ah, (uint2*)al, n4);
    gemm_mma_kernel<<<ggrid, 256, GEMM_SMEM>>>(ah, al, wth + 1 * WSZ, wtl + 1 * WSZ, bk,
                                               nullptr, kh_, kl_, 2);
    split_bf16_kernel<<<n4 / 256, 256>>>((const float4*)values, (uint2*)ah, (uint2*)al, n4);
    gemm_mma_kernel<<<ggrid, 256, GEMM_SMEM>>>(ah, al, wth + 2 * WSZ, wtl + 2 * WSZ, bv,
                                               nullptr, vh_, vl_, 2);

    // Attention (tensor-core)
    dim3 agrid(Ln / 128, Hn, Bn);        // (16, 16, 4)
    attn_mma_kernel<<<agrid, 256, ATTN_SMEM>>>(qh_, ql_, kh_, kl_, vh_, vl_, ctxbuf);

    // Output projection (mode 0 -> d_out fp32)
    split_bf16_kernel<<<n4 / 256, 256>>>((const float4*)ctxbuf, (uint2*)ah, (uint2*)al, n4);
    gemm_mma_kernel<<<ggrid, 256, GEMM_SMEM>>>(ah, al, wth + 3 * WSZ, wtl + 3 * WSZ, bo,
                                               (float*)d_out, nullptr, nullptr, 0);
}